// round 16
// baseline (speedup 1.0000x reference)
#include <cuda_runtime.h>
#include <math.h>

#define TT   8192
#define DIN  2048
#define DD   512
#define HH   512
#define AA   18

#define CL   16      // cluster size (CTAs)
#define THR  512     // threads per CTA
#define NW   (THR/32)
#define XBYTES ((CL - 1) * 128)   // expected remote bytes per step = 1920

// ---------------- scratch ------------------------------------------------------
__device__ float g_z1 [TT * DD];
__device__ float g_z2 [TT * DD];
__device__ float g_X  [TT * 3 * HH];
__device__ float g_seq[TT * HH];

// ---------------- asm helpers --------------------------------------------------
__device__ __forceinline__ unsigned smem_u32(const void* p) {
    unsigned a;
    asm("{ .reg .u64 t; cvta.to.shared.u64 t, %1; cvt.u32.u64 %0, t; }" : "=r"(a) : "l"(p));
    return a;
}
__device__ __forceinline__ unsigned ctarank() {
    unsigned r; asm("mov.u32 %0, %%cluster_ctarank;" : "=r"(r)); return r;
}
__device__ __forceinline__ unsigned mapa_u32(unsigned addr, unsigned rank) {
    unsigned r; asm("mapa.shared::cluster.u32 %0, %1, %2;" : "=r"(r) : "r"(addr), "r"(rank));
    return r;
}
__device__ __forceinline__ unsigned long long pk2(float lo, float hi) {
    unsigned long long r; asm("mov.b64 %0, {%1,%2};" : "=l"(r) : "f"(lo), "f"(hi)); return r;
}
__device__ __forceinline__ void up2(unsigned long long v, float& lo, float& hi) {
    asm("mov.b64 {%0,%1}, %2;" : "=f"(lo), "=f"(hi) : "l"(v));
}
__device__ __forceinline__ unsigned long long ffma2(unsigned long long a,
                                                    unsigned long long b,
                                                    unsigned long long c) {
    unsigned long long d;
    asm("fma.rn.f32x2 %0, %1, %2, %3;" : "=l"(d) : "l"(a), "l"(b), "l"(c));
    return d;
}
// sigmoid: MUFU.EX2-based exp + rcp.approx (avoids div.rn expansion)
__device__ __forceinline__ float sigmoid_rcp(float x) {
    float e = __expf(-x);
    float r;
    asm("rcp.approx.f32 %0, %1;" : "=f"(r) : "f"(1.0f + e));
    return r;
}
// mbarrier primitives
__device__ __forceinline__ void mbar_init(unsigned addr, unsigned cnt) {
    asm volatile("mbarrier.init.shared::cta.b64 [%0], %1;" :: "r"(addr), "r"(cnt) : "memory");
}
__device__ __forceinline__ void mbar_arm(unsigned addr, unsigned txbytes) {
    asm volatile("mbarrier.arrive.expect_tx.shared::cta.b64 _, [%0], %1;"
                 :: "r"(addr), "r"(txbytes) : "memory");
}
__device__ __forceinline__ void mbar_wait(unsigned addr, unsigned parity) {
    asm volatile(
        "{\n\t.reg .pred P;\n"
        "LW_%=:\n\t"
        "mbarrier.try_wait.parity.acquire.cluster.shared::cta.b64 P, [%0], %1, 0x989680;\n\t"
        "@P bra LD_%=;\n\t"
        "bra LW_%=;\n"
        "LD_%=:\n\t}"
        :: "r"(addr), "r"(parity) : "memory");
}
// 128-byte SMEM->peer-SMEM bulk copy, completion on peer's mbarrier (tx bytes)
__device__ __forceinline__ void bulk_s2s(unsigned dst_cluster, unsigned src_cta,
                                         unsigned bytes, unsigned mbar_cluster) {
    asm volatile(
        "cp.async.bulk.shared::cluster.shared::cta.mbarrier::complete_tx::bytes "
        "[%0], [%1], %2, [%3];"
        :: "r"(dst_cluster), "r"(src_cta), "r"(bytes), "r"(mbar_cluster) : "memory");
}

// ---------------- 128x128x8 register-blocked SGEMM -----------------------------
__global__ __launch_bounds__(256) void sgemm128(
    const float* __restrict__ A, const float* __restrict__ B,
    const float* __restrict__ bias, float* __restrict__ C,
    int M, int N, int K, int relu)
{
    __shared__ float As[8][128];
    __shared__ float Bs[8][128];
    int tid  = threadIdx.x;
    int brow = blockIdx.y * 128, bcol = blockIdx.x * 128;
    int aRow = tid >> 1,   aCol = (tid & 1) * 4;
    int bRow = tid >> 5,   bCol = (tid & 31) * 4;
    int trow = (tid >> 4) * 8, tcol = (tid & 15) * 8;

    const float* Ap = A + (size_t)(brow + aRow) * K + aCol;
    const float* Bp = B + (size_t)bRow * N + bcol + bCol;

    float acc[8][8];
#pragma unroll
    for (int i = 0; i < 8; i++)
#pragma unroll
        for (int j = 0; j < 8; j++) acc[i][j] = 0.f;

    for (int k0 = 0; k0 < K; k0 += 8) {
        float4 a4 = *(const float4*)Ap;  Ap += 8;
        float4 b4 = *(const float4*)Bp;  Bp += (size_t)8 * N;
        As[aCol + 0][aRow] = a4.x;
        As[aCol + 1][aRow] = a4.y;
        As[aCol + 2][aRow] = a4.z;
        As[aCol + 3][aRow] = a4.w;
        *(float4*)&Bs[bRow][bCol] = b4;
        __syncthreads();
#pragma unroll
        for (int kk = 0; kk < 8; kk++) {
            float fa[8], fb[8];
            *(float4*)&fa[0] = *(const float4*)&As[kk][trow];
            *(float4*)&fa[4] = *(const float4*)&As[kk][trow + 4];
            *(float4*)&fb[0] = *(const float4*)&Bs[kk][tcol];
            *(float4*)&fb[4] = *(const float4*)&Bs[kk][tcol + 4];
#pragma unroll
            for (int i = 0; i < 8; i++)
#pragma unroll
                for (int j = 0; j < 8; j++)
                    acc[i][j] = fmaf(fa[i], fb[j], acc[i][j]);
        }
        __syncthreads();
    }

#pragma unroll
    for (int i = 0; i < 8; i++) {
        float* cp = C + (size_t)(brow + trow + i) * N + bcol + tcol;
#pragma unroll
        for (int j = 0; j < 8; j++) {
            float v = acc[i][j] + bias[bcol + tcol + j];
            if (relu) v = v > 0.f ? v : 0.f;
            cp[j] = v;
        }
    }
}

// ---------------- GRU scan: 16-CTA cluster, aggregated bulk broadcast ----------
// 256 warps cluster-wide; warp W owns hidden i0=2W, i1=2W+1 (6 gate columns),
// weights register-resident packed f32x2. h double-buffered in SMEM. Exchange:
// each warp STSes its 2 values into the CTA's contiguous 128B slice of the
// target buffer, __syncthreads, then lanes 0..14 of warp 0 each bulk-copy the
// 128B slice to one peer CTA (cp.async.bulk, complete_tx on the peer's
// mbarrier). Dest mbarrier sees 15 arrivals (1920 bytes) per step instead of
// 256 st.async arrivals.
__global__ void __cluster_dims__(CL, 1, 1) __launch_bounds__(THR, 1)
gru_cluster_k(const float* __restrict__ X,   // [T, 3H]
              const float* __restrict__ Ug,  // [H, 3H]
              const float* __restrict__ bg,  // [2, 3H]
              const float* __restrict__ h0,  // [1, H]
              float* __restrict__ seq)       // [T, H]
{
    __shared__ __align__(16) float hbuf[2][HH];
    __shared__ __align__(8) unsigned long long mbar[2];

    const int tid = threadIdx.x;
    const int wid = tid >> 5;
    const int l   = tid & 31;
    const unsigned rank = ctarank();
    const int W  = (int)rank * NW + wid;   // 0..255
    const int i0 = 2 * W;
    const int half = l >> 4;               // 0: finalize i0, 1: finalize i1
    const int col  = i0 + half;

    // ---- register-resident packed weights (float4-load friendly layout)
    unsigned long long wp[6][8];
    {
        const int i1 = i0 + 1;
        const int cols[6] = { i0, 512 + i0, 1024 + i0, i1, 512 + i1, 1024 + i1 };
#pragma unroll
        for (int j = 0; j < 4; j++) {
            int k = 4 * l + 128 * j;
            const float* r0 = Ug + (size_t)k * 1536;
            const float* r1 = r0 + 1536;
            const float* r2 = r1 + 1536;
            const float* r3 = r2 + 1536;
#pragma unroll
            for (int g = 0; g < 6; g++) {
                wp[g][2 * j]     = pk2(r0[cols[g]], r1[cols[g]]);
                wp[g][2 * j + 1] = pk2(r2[cols[g]], r3[cols[g]]);
            }
        }
    }

    const float brz = bg[1536 + col];
    const float brr = bg[1536 + 512 + col];
    const float brh = bg[1536 + 1024 + col];

    // this CTA's contiguous 128B slice (columns 32*rank .. 32*rank+31)
    const unsigned src0 = smem_u32(&hbuf[0][32 * (int)rank]);
    const unsigned src1 = smem_u32(&hbuf[1][32 * (int)rank]);
    const unsigned lm0 = smem_u32(&mbar[0]);
    const unsigned lm1 = smem_u32(&mbar[1]);

    // lanes 0..14 of warp 0: one peer each (skip self)
    unsigned dst0 = 0, dst1 = 0, rmb0 = 0, rmb1 = 0;
    const bool sender = (tid < CL - 1);
    if (sender) {
        unsigned peer = (unsigned)tid + ((unsigned)tid >= rank ? 1u : 0u);
        dst0 = mapa_u32(src0, peer);
        dst1 = mapa_u32(src1, peer);
        rmb0 = mapa_u32(lm0, peer);
        rmb1 = mapa_u32(lm1, peer);
    }

    if (tid == 0) {
        mbar_init(lm0, 1);
        mbar_init(lm1, 1);
        mbar_arm(lm0, XBYTES);   // phase 0 of each buffer
        mbar_arm(lm1, XBYTES);
        asm volatile("fence.mbarrier_init.release.cluster;" ::: "memory");
    }
    hbuf[0][tid] = h0[tid];
    __syncthreads();
    asm volatile("barrier.cluster.arrive.aligned;" ::: "memory");
    asm volatile("barrier.cluster.wait.aligned;"   ::: "memory");

    // one-step body: dot against hrow, gates, return hn for this lane's col
    auto gates = [&](const float* hrow, float xz, float xr, float xh) -> float {
        const float hprev = hrow[col];
        unsigned long long a0 = 0, a1 = 0, a2 = 0, a3 = 0, a4 = 0, a5 = 0;
        const float4* h4p = (const float4*)hrow + l;
#pragma unroll
        for (int j = 0; j < 4; j++) {
            float4 h4 = h4p[32 * j];
            unsigned long long hA = pk2(h4.x, h4.y);
            unsigned long long hB = pk2(h4.z, h4.w);
            a0 = ffma2(wp[0][2 * j], hA, a0);
            a1 = ffma2(wp[1][2 * j], hA, a1);
            a2 = ffma2(wp[2][2 * j], hA, a2);
            a3 = ffma2(wp[3][2 * j], hA, a3);
            a4 = ffma2(wp[4][2 * j], hA, a4);
            a5 = ffma2(wp[5][2 * j], hA, a5);
            a0 = ffma2(wp[0][2 * j + 1], hB, a0);
            a1 = ffma2(wp[1][2 * j + 1], hB, a1);
            a2 = ffma2(wp[2][2 * j + 1], hB, a2);
            a3 = ffma2(wp[3][2 * j + 1], hB, a3);
            a4 = ffma2(wp[4][2 * j + 1], hB, a4);
            a5 = ffma2(wp[5][2 * j + 1], hB, a5);
        }
        float s0, s1, s2, s3, s4, s5;
        { float lo, hi;
          up2(a0, lo, hi); s0 = lo + hi;
          up2(a1, lo, hi); s1 = lo + hi;
          up2(a2, lo, hi); s2 = lo + hi;
          up2(a3, lo, hi); s3 = lo + hi;
          up2(a4, lo, hi); s4 = lo + hi;
          up2(a5, lo, hi); s5 = lo + hi; }

        // folded warp reduction
        s0 += __shfl_xor_sync(0xffffffffu, s0, 16);
        s1 += __shfl_xor_sync(0xffffffffu, s1, 16);
        s2 += __shfl_xor_sync(0xffffffffu, s2, 16);
        s3 += __shfl_xor_sync(0xffffffffu, s3, 16);
        s4 += __shfl_xor_sync(0xffffffffu, s4, 16);
        s5 += __shfl_xor_sync(0xffffffffu, s5, 16);
        float uz = half ? s3 : s0;
        float ur = half ? s4 : s1;
        float uh = half ? s5 : s2;
#pragma unroll
        for (int o = 8; o > 0; o >>= 1) {
            uz += __shfl_xor_sync(0xffffffffu, uz, o);
            ur += __shfl_xor_sync(0xffffffffu, ur, o);
            uh += __shfl_xor_sync(0xffffffffu, uh, o);
        }

        const float zt = sigmoid_rcp(xz + uz + brz);
        const float rt = sigmoid_rcp(xr + ur + brr);
        const float hc = sigmoid_rcp(xh + rt * (uh + brh));
        return zt * hprev + (1.f - zt) * hc;
    };

    // X regs for the current step (t=0 preloaded)
    float xz = X[col], xr = X[512 + col], xh = X[1024 + col];
    unsigned ph = 0;

    for (int t = 0; t < TT; t += 2) {
        // ===== step A (t): read hbuf[0], publish into hbuf[1] =====
        const float* xpn = X + (size_t)(t + 1) * 1536 + col;
        float nxz = xpn[0], nxr = xpn[512], nxh = xpn[1024];

        if (t) { mbar_wait(lm0, ph ^ 1); if (tid == 0) mbar_arm(lm0, XBYTES); }

        float hn = gates(hbuf[0], xz, xr, xh);
        if ((l & 15) == 0) {
            hbuf[1][col] = hn;                       // local slice
            seq[(size_t)t * HH + col] = hn;          // persist
        }
        __syncthreads();
        if (sender) {
            asm volatile("fence.proxy.async.shared::cta;" ::: "memory");
            bulk_s2s(dst1, src1, 128, rmb1);
        }
        xz = nxz; xr = nxr; xh = nxh;

        // ===== step B (t+1): read hbuf[1], publish into hbuf[0] =====
        const int tn = (t + 2 < TT) ? (t + 2) : (TT - 1);
        const float* xpn2 = X + (size_t)tn * 1536 + col;
        nxz = xpn2[0]; nxr = xpn2[512]; nxh = xpn2[1024];

        mbar_wait(lm1, ph); if (tid == 0) mbar_arm(lm1, XBYTES);

        hn = gates(hbuf[1], xz, xr, xh);
        if ((l & 15) == 0) {
            hbuf[0][col] = hn;
            seq[(size_t)(t + 1) * HH + col] = hn;
        }
        __syncthreads();
        if (sender && t + 2 < TT) {
            asm volatile("fence.proxy.async.shared::cta;" ::: "memory");
            bulk_s2s(dst0, src0, 128, rmb0);
        }
        xz = nxz; xr = nxr; xh = nxh;

        ph ^= 1;
    }

    asm volatile("barrier.cluster.arrive.aligned;" ::: "memory");
    asm volatile("barrier.cluster.wait.aligned;"   ::: "memory");
}

// ---------------- policy / value heads -----------------------------------------
__global__ __launch_bounds__(256) void head_k(
    const float* __restrict__ seq,
    const float* __restrict__ Wp, const float* __restrict__ bp,
    const float* __restrict__ Wv, const float* __restrict__ bv,
    float* __restrict__ out)
{
    int warp = blockIdx.x * (blockDim.x >> 5) + (threadIdx.x >> 5);
    int l = threadIdx.x & 31;
    if (warp >= TT) return;
    const float* s = seq + (size_t)warp * HH;

    const float* wptr;
    int stride;
    float acc;
    if (l < AA)       { wptr = Wp + l; stride = AA; acc = bp[l]; }
    else if (l == AA) { wptr = Wv;     stride = 1;  acc = bv[0]; }
    else              { wptr = Wp;     stride = 0;  acc = 0.f; }

#pragma unroll 8
    for (int k = 0; k < HH; k++)
        acc = fmaf(s[k], wptr[(size_t)k * stride], acc);

    float lv = (l < AA) ? acc : -INFINITY;
    float m = lv;
#pragma unroll
    for (int o = 16; o > 0; o >>= 1) m = fmaxf(m, __shfl_xor_sync(0xffffffffu, m, o));
    float e = (l < AA) ? __expf(acc - m) : 0.f;
    float ssum = e;
#pragma unroll
    for (int o = 16; o > 0; o >>= 1) ssum += __shfl_xor_sync(0xffffffffu, ssum, o);

    if (l < AA)  out[(size_t)warp * AA + l] = e / ssum;       // policy
    if (l == AA) out[(size_t)TT * AA + warp] = acc;           // value
}

__global__ void ht_k(const float* __restrict__ seq, float* __restrict__ out) {
    int i = threadIdx.x;
    out[(size_t)TT * (AA + 1) + i] = seq[(size_t)(TT - 1) * HH + i];
}

// ---------------- launch --------------------------------------------------------
extern "C" void kernel_launch(void* const* d_in, const int* in_sizes, int n_in,
                              void* d_out, int out_size)
{
    const float* x  = (const float*)d_in[0];
    const float* h0 = (const float*)d_in[1];
    const float* W1 = (const float*)d_in[2];
    const float* b1 = (const float*)d_in[3];
    const float* W2 = (const float*)d_in[4];
    const float* b2 = (const float*)d_in[5];
    const float* Wg = (const float*)d_in[6];
    const float* Ug = (const float*)d_in[7];
    const float* bg = (const float*)d_in[8];
    const float* Wp = (const float*)d_in[9];
    const float* bp = (const float*)d_in[10];
    const float* Wv = (const float*)d_in[11];
    const float* bv = (const float*)d_in[12];
    float* out = (float*)d_out;

    float *z1, *z2, *X, *seq;
    cudaGetSymbolAddress((void**)&z1,  g_z1);
    cudaGetSymbolAddress((void**)&z2,  g_z2);
    cudaGetSymbolAddress((void**)&X,   g_X);
    cudaGetSymbolAddress((void**)&seq, g_seq);

    cudaFuncSetAttribute(gru_cluster_k,
                         cudaFuncAttributeNonPortableClusterSizeAllowed, 1);

    // 1) MLP front-end + GRU input projection
    dim3 g1(DD / 128, TT / 128);
    sgemm128<<<g1, 256>>>(x,  W1, b1, z1, TT, DD, DIN, 1);
    sgemm128<<<g1, 256>>>(z1, W2, b2, z2, TT, DD, DD, 1);
    dim3 g3((3 * HH) / 128, TT / 128);
    sgemm128<<<g3, 256>>>(z2, Wg, bg /*row 0*/, X, TT, 3 * HH, DD, 0);

    // 2) sequential GRU scan (16-CTA cluster, aggregated bulk broadcast)
    gru_cluster_k<<<CL, THR>>>(X, Ug, bg, h0, seq);

    // 3) heads + final hidden state
    head_k<<<(TT * 32 + 255) / 256, 256>>>(seq, Wp, bp, Wv, bv, out);
    ht_k<<<1, HH>>>(seq, out);
}